// round 4
// baseline (speedup 1.0000x reference)
#include <cuda_runtime.h>

// Row-wise cosine similarity * 0.5 over [B=16384, D=4096] fp32.
// HBM-bound streaming reduction: 512 MiB read. v2: one WARP per row
// (no __syncthreads, no smem, shuffle-only reduce) + __ldcs streaming
// loads (evict-first; data has zero reuse).

#define D_DIM 4096
#define THREADS 256
#define WARPS_PER_CTA (THREADS / 32)
// Per row: 1024 float4 per input; per lane: 32 float4 per input -> 8 iters x 4.

__global__ __launch_bounds__(THREADS) void cosine_rows_warp_kernel(
    const float* __restrict__ x1,
    const float* __restrict__ x2,
    float* __restrict__ out)
{
    const int warp_in_cta = threadIdx.x >> 5;
    const int lane = threadIdx.x & 31;
    const int row = blockIdx.x * WARPS_PER_CTA + warp_in_cta;

    const float4* r1 = reinterpret_cast<const float4*>(x1 + (size_t)row * D_DIM);
    const float4* r2 = reinterpret_cast<const float4*>(x2 + (size_t)row * D_DIM);

    float dot = 0.f, sx = 0.f, sy = 0.f;

#pragma unroll
    for (int it = 0; it < 8; ++it) {
        float4 a[4], b[4];
#pragma unroll
        for (int j = 0; j < 4; ++j) {
            a[j] = __ldcs(&r1[lane + (it * 4 + j) * 32]);
            b[j] = __ldcs(&r2[lane + (it * 4 + j) * 32]);
        }
#pragma unroll
        for (int j = 0; j < 4; ++j) {
            dot = fmaf(a[j].x, b[j].x, dot);
            dot = fmaf(a[j].y, b[j].y, dot);
            dot = fmaf(a[j].z, b[j].z, dot);
            dot = fmaf(a[j].w, b[j].w, dot);
            sx  = fmaf(a[j].x, a[j].x, sx);
            sx  = fmaf(a[j].y, a[j].y, sx);
            sx  = fmaf(a[j].z, a[j].z, sx);
            sx  = fmaf(a[j].w, a[j].w, sx);
            sy  = fmaf(b[j].x, b[j].x, sy);
            sy  = fmaf(b[j].y, b[j].y, sy);
            sy  = fmaf(b[j].z, b[j].z, sy);
            sy  = fmaf(b[j].w, b[j].w, sy);
        }
    }

    // Shuffle-only reduction (no barrier, no smem)
#pragma unroll
    for (int off = 16; off > 0; off >>= 1) {
        dot += __shfl_down_sync(0xFFFFFFFFu, dot, off);
        sx  += __shfl_down_sync(0xFFFFFFFFu, sx,  off);
        sy  += __shfl_down_sync(0xFFFFFFFFu, sy,  off);
    }

    if (lane == 0) {
        out[row] = 0.5f * dot * rsqrtf(sx * sy);
    }
}

extern "C" void kernel_launch(void* const* d_in, const int* in_sizes, int n_in,
                              void* d_out, int out_size)
{
    const float* x1 = (const float*)d_in[0];
    const float* x2 = (const float*)d_in[1];
    float* out = (float*)d_out;
    const int B = out_size;  // 16384 rows
    cosine_rows_warp_kernel<<<B / WARPS_PER_CTA, THREADS>>>(x1, x2, out);
}